// round 4
// baseline (speedup 1.0000x reference)
#include <cuda_runtime.h>
#include <cuda_bf16.h>
#include <math_constants.h>

// BBOX_XFORM_CLIP = log(1000/16)
#define BBOX_XFORM_CLIP 4.135166556742356f

#define ROWS 8                       // rows per tile
#define THREADS 256                  // 8 warps, 1 row per warp
#define CTAS_PER_SM 7
#define NUM_SMS 148

#define LOG_TILE_BYTES  (ROWS * 81 * 4)    // 2592
#define PR_TILE_BYTES   (ROWS * 16)        // 128
#define BOX_TILE_BYTES  (ROWS * 81 * 16)   // 10368
#define SC_TILE_BYTES   (ROWS * 81 * 4)    // 2592
#define TX_BYTES (LOG_TILE_BYTES + 2 * PR_TILE_BYTES)  // 2848

// img dims may arrive as int32 or float32; disambiguate by plausibility.
__device__ __forceinline__ float load_dim(const void* p) {
    int iv = *(const int*)p;
    if (iv > 0 && iv < (1 << 20)) return (float)iv;
    return __int_as_float(iv);
}

__device__ __forceinline__ void mbar_wait(unsigned mbar, int phase) {
    asm volatile(
        "{\n\t"
        ".reg .pred P;\n"
        "W%=:\n\t"
        "mbarrier.try_wait.parity.acquire.cta.shared::cta.b64 P, [%0], %1, 0x989680;\n\t"
        "@!P bra W%=;\n\t"
        "}"
        :: "r"(mbar), "r"(phase) : "memory");
}

__device__ __forceinline__ void bulk_load(unsigned dst, const void* src,
                                          int bytes, unsigned mbar) {
    asm volatile(
        "cp.async.bulk.shared::cta.global.mbarrier::complete_tx::bytes "
        "[%0], [%1], %2, [%3];"
        :: "r"(dst), "l"(src), "r"(bytes), "r"(mbar) : "memory");
}

__global__ void __launch_bounds__(THREADS)
postproc_kernel(const float* __restrict__ logits,       // [N,81]
                const float* __restrict__ regr,         // [N,4]
                const float* __restrict__ prop,         // [N,4]
                const void*  __restrict__ imw_p,
                const void*  __restrict__ imh_p,
                float* __restrict__ boxes_out,          // [N*81,4]
                float* __restrict__ scores_out,         // [N*81]
                int N)
{
    __shared__ alignas(16) float  s_log[2][ROWS * 81];       // 2x2592B
    __shared__ alignas(16) float4 s_pr [2][ROWS];            // 2x 128B
    __shared__ alignas(16) float4 s_rg [2][ROWS];            // 2x 128B
    __shared__ alignas(16) float  s_box[2][ROWS * 81 * 4];   // 2x10368B
    __shared__ alignas(16) float  s_sc [2][ROWS * 81];       // 2x2592B
    __shared__ alignas(8)  unsigned long long s_mbar[2];

    const int warp = threadIdx.x >> 5;
    const int lane = threadIdx.x & 31;

    const float wmax = load_dim(imw_p) - 1.0f;
    const float hmax = load_dim(imh_p) - 1.0f;

    const int T      = N / ROWS;          // full tiles
    const int stride = gridDim.x;

    const unsigned mb0 = (unsigned)__cvta_generic_to_shared(&s_mbar[0]);
    const unsigned mb1 = (unsigned)__cvta_generic_to_shared(&s_mbar[1]);
    const unsigned dlog0 = (unsigned)__cvta_generic_to_shared(s_log[0]);
    const unsigned dlog1 = (unsigned)__cvta_generic_to_shared(s_log[1]);
    const unsigned dpr0  = (unsigned)__cvta_generic_to_shared(s_pr[0]);
    const unsigned dpr1  = (unsigned)__cvta_generic_to_shared(s_pr[1]);
    const unsigned drg0  = (unsigned)__cvta_generic_to_shared(s_rg[0]);
    const unsigned drg1  = (unsigned)__cvta_generic_to_shared(s_rg[1]);

    if (threadIdx.x == 0) {
        asm volatile("mbarrier.init.shared.b64 [%0], 1;" :: "r"(mb0) : "memory");
        asm volatile("mbarrier.init.shared.b64 [%0], 1;" :: "r"(mb1) : "memory");
        asm volatile("fence.proxy.async.shared::cta;" ::: "memory");
    }
    __syncthreads();

    // prologue: kick off load for first tile into buffer 0
    if (threadIdx.x == 0 && blockIdx.x < T) {
        int t0 = blockIdx.x;
        asm volatile("mbarrier.arrive.expect_tx.shared::cta.b64 _, [%0], %1;"
                     :: "r"(mb0), "r"(TX_BYTES) : "memory");
        bulk_load(dlog0, (const char*)logits + (size_t)t0 * LOG_TILE_BYTES,
                  LOG_TILE_BYTES, mb0);
        bulk_load(dpr0,  (const char*)prop   + (size_t)t0 * PR_TILE_BYTES,
                  PR_TILE_BYTES, mb0);
        bulk_load(drg0,  (const char*)regr   + (size_t)t0 * PR_TILE_BYTES,
                  PR_TILE_BYTES, mb0);
    }

    int ph0 = 0, ph1 = 0;
    int p = 0;
    for (int t = blockIdx.x; t < T; t += stride, p ^= 1) {
        // issue load for next tile into the other buffer (free since last iter)
        const int tn = t + stride;
        if (threadIdx.x == 0 && tn < T) {
            const unsigned mb   = p ? mb0   : mb1;
            const unsigned dlog = p ? dlog0 : dlog1;
            const unsigned dpr  = p ? dpr0  : dpr1;
            const unsigned drg  = p ? drg0  : drg1;
            asm volatile("mbarrier.arrive.expect_tx.shared::cta.b64 _, [%0], %1;"
                         :: "r"(mb), "r"(TX_BYTES) : "memory");
            bulk_load(dlog, (const char*)logits + (size_t)tn * LOG_TILE_BYTES,
                      LOG_TILE_BYTES, mb);
            bulk_load(dpr,  (const char*)prop   + (size_t)tn * PR_TILE_BYTES,
                      PR_TILE_BYTES, mb);
            bulk_load(drg,  (const char*)regr   + (size_t)tn * PR_TILE_BYTES,
                      PR_TILE_BYTES, mb);
        }

        // wait for current tile's inputs
        {
            const unsigned mb = p ? mb1 : mb0;
            const int ph = p ? ph1 : ph0;
            mbar_wait(mb, ph);
            if (p) ph1 ^= 1; else ph0 ^= 1;
        }

        // ---------------- softmax over 81 logits (from SMEM) ----------------
        const float* lrow = s_log[p] + warp * 81;
        float v0 = lrow[lane];
        float v1 = lrow[lane + 32];
        float v2 = (lane < 17) ? lrow[lane + 64] : -CUDART_INF_F;

        float m = fmaxf(fmaxf(v0, v1), v2);
        #pragma unroll
        for (int o = 16; o; o >>= 1)
            m = fmaxf(m, __shfl_xor_sync(0xffffffffu, m, o));

        float e0 = __expf(v0 - m);
        float e1 = __expf(v1 - m);
        float e2 = (lane < 17) ? __expf(v2 - m) : 0.0f;

        float s = e0 + e1 + e2;
        #pragma unroll
        for (int o = 16; o; o >>= 1)
            s += __shfl_xor_sync(0xffffffffu, s, o);
        const float inv = 1.0f / s;

        // ---------------- bbox decode (broadcast LDS) ----------------
        const float4 b  = s_pr[p][warp];
        const float4 rc = s_rg[p][warp];

        const float w  = b.z - b.x + 1.0f;
        const float h  = b.w - b.y + 1.0f;
        const float cx = b.x + 0.5f * w;
        const float cy = b.y + 0.5f * h;

        const float dx = rc.x * 0.1f;
        const float dy = rc.y * 0.1f;
        const float dw = fminf(rc.z * 0.2f, BBOX_XFORM_CLIP);
        const float dh = fminf(rc.w * 0.2f, BBOX_XFORM_CLIP);

        const float pcx = dx * w + cx;
        const float pcy = dy * h + cy;
        const float pw  = __expf(dw) * w;
        const float ph_ = __expf(dh) * h;

        float x1 = pcx - 0.5f * pw;
        float y1 = pcy - 0.5f * ph_;
        float x2 = pcx + 0.5f * pw - 1.0f;
        float y2 = pcy + 0.5f * ph_ - 1.0f;

        x1 = fminf(fmaxf(x1, 0.0f), wmax);
        y1 = fminf(fmaxf(y1, 0.0f), hmax);
        x2 = fminf(fmaxf(x2, 0.0f), wmax);
        y2 = fminf(fmaxf(y2, 0.0f), hmax);
        const float4 box = make_float4(x1, y1, x2, y2);

        // ---------------- stage outputs ----------------
        float4* sb = reinterpret_cast<float4*>(s_box[p]) + warp * 81;
        sb[lane]      = box;
        sb[lane + 32] = box;
        if (lane < 17) sb[lane + 64] = box;

        float* ss = s_sc[p] + warp * 81;
        ss[lane]      = e0 * inv;
        ss[lane + 32] = e1 * inv;
        if (lane < 17) ss[lane + 64] = e2 * inv;

        __syncthreads();

        if (threadIdx.x == 0) {
            asm volatile("fence.proxy.async.shared::cta;" ::: "memory");
            unsigned sb_a = (unsigned)__cvta_generic_to_shared(s_box[p]);
            unsigned ss_a = (unsigned)__cvta_generic_to_shared(s_sc[p]);
            char* gb = (char*)boxes_out  + (size_t)t * BOX_TILE_BYTES;
            char* gs = (char*)scores_out + (size_t)t * SC_TILE_BYTES;
            asm volatile("cp.async.bulk.global.shared::cta.bulk_group [%0], [%1], %2;"
                         :: "l"(gb), "r"(sb_a), "n"(BOX_TILE_BYTES) : "memory");
            asm volatile("cp.async.bulk.global.shared::cta.bulk_group [%0], [%1], %2;"
                         :: "l"(gs), "r"(ss_a), "n"(SC_TILE_BYTES) : "memory");
            asm volatile("cp.async.bulk.commit_group;" ::: "memory");
            // allow one group in flight; buffer p^1's store has completed
            asm volatile("cp.async.bulk.wait_group.read 1;" ::: "memory");
        }
        __syncthreads();
    }

    // ---------------- tail rows (N % ROWS), direct path, block 0 ----------
    const int rem = N - T * ROWS;
    if (blockIdx.x == 0 && warp < rem) {
        const int n = T * ROWS + warp;
        const float* lrow = logits + (size_t)n * 81;
        float v0 = lrow[lane];
        float v1 = lrow[lane + 32];
        float v2 = (lane < 17) ? lrow[lane + 64] : -CUDART_INF_F;
        float m = fmaxf(fmaxf(v0, v1), v2);
        #pragma unroll
        for (int o = 16; o; o >>= 1)
            m = fmaxf(m, __shfl_xor_sync(0xffffffffu, m, o));
        float e0 = __expf(v0 - m);
        float e1 = __expf(v1 - m);
        float e2 = (lane < 17) ? __expf(v2 - m) : 0.0f;
        float s = e0 + e1 + e2;
        #pragma unroll
        for (int o = 16; o; o >>= 1)
            s += __shfl_xor_sync(0xffffffffu, s, o);
        const float inv = 1.0f / s;

        const float4 b  = reinterpret_cast<const float4*>(prop)[n];
        const float4 rc = reinterpret_cast<const float4*>(regr)[n];
        const float w  = b.z - b.x + 1.0f;
        const float h  = b.w - b.y + 1.0f;
        const float cx = b.x + 0.5f * w;
        const float cy = b.y + 0.5f * h;
        const float dx = rc.x * 0.1f;
        const float dy = rc.y * 0.1f;
        const float dw = fminf(rc.z * 0.2f, BBOX_XFORM_CLIP);
        const float dh = fminf(rc.w * 0.2f, BBOX_XFORM_CLIP);
        const float pcx = dx * w + cx;
        const float pcy = dy * h + cy;
        const float pw  = __expf(dw) * w;
        const float ph_ = __expf(dh) * h;
        float x1 = fminf(fmaxf(pcx - 0.5f * pw, 0.0f), wmax);
        float y1 = fminf(fmaxf(pcy - 0.5f * ph_, 0.0f), hmax);
        float x2 = fminf(fmaxf(pcx + 0.5f * pw - 1.0f, 0.0f), wmax);
        float y2 = fminf(fmaxf(pcy + 0.5f * ph_ - 1.0f, 0.0f), hmax);
        const float4 box = make_float4(x1, y1, x2, y2);

        float4* bo = reinterpret_cast<float4*>(boxes_out) + (size_t)n * 81;
        bo[lane]      = box;
        bo[lane + 32] = box;
        if (lane < 17) bo[lane + 64] = box;
        float* so = scores_out + (size_t)n * 81;
        so[lane]      = e0 * inv;
        so[lane + 32] = e1 * inv;
        if (lane < 17) so[lane + 64] = e2 * inv;
    }

    // drain outstanding bulk-store groups before CTA retires
    if (threadIdx.x == 0)
        asm volatile("cp.async.bulk.wait_group.read 0;" ::: "memory");
}

extern "C" void kernel_launch(void* const* d_in, const int* in_sizes, int n_in,
                              void* d_out, int out_size) {
    const float* logits = (const float*)d_in[0];
    const float* regr   = (const float*)d_in[1];
    const float* prop   = (const float*)d_in[2];
    const void*  imw    = d_in[3];
    const void*  imh    = d_in[4];

    const int N = in_sizes[0] / 81;          // 262144

    float* boxes  = (float*)d_out;           // N*81*4 floats
    float* scores = boxes + (size_t)N * 81 * 4;

    const int blocks = CTAS_PER_SM * NUM_SMS;    // 1036 persistent CTAs
    postproc_kernel<<<blocks, THREADS>>>(logits, regr, prop, imw, imh,
                                         boxes, scores, N);
}

// round 5
// speedup vs baseline: 1.0439x; 1.0439x over previous
#include <cuda_runtime.h>
#include <cuda_bf16.h>
#include <math_constants.h>

// BBOX_XFORM_CLIP = log(1000/16)
#define BBOX_XFORM_CLIP 4.135166556742356f

#define ROWS_PER_BLOCK 32            // 32 rows * 81 classes
#define THREADS 512                  // 16 warps, 2 rows each

#define BOX_TILE_BYTES   (ROWS_PER_BLOCK * 81 * 16)   // 41472
#define SC_TILE_BYTES    (ROWS_PER_BLOCK * 81 * 4)    // 10368

// img dims may arrive as int32 or float32; disambiguate by plausibility.
__device__ __forceinline__ float load_dim(const void* p) {
    int iv = *(const int*)p;
    if (iv > 0 && iv < (1 << 20)) return (float)iv;
    return __int_as_float(iv);
}

__global__ void __launch_bounds__(THREADS)
postproc_kernel(const float* __restrict__ logits,       // [N,81]
                const float* __restrict__ regr,         // [N,4]
                const float* __restrict__ prop,         // [N,4]
                const void*  __restrict__ imw_p,
                const void*  __restrict__ imh_p,
                float* __restrict__ boxes_out,          // [N*81,4]
                float* __restrict__ scores_out,         // [N*81]
                int N)
{
    __shared__ alignas(16) float s_boxes [ROWS_PER_BLOCK * 81 * 4];  // 41472 B
    __shared__ alignas(16) float s_scores[ROWS_PER_BLOCK * 81];      // 10368 B

    const int warp = threadIdx.x >> 5;
    const int lane = threadIdx.x & 31;
    const int r0   = blockIdx.x * ROWS_PER_BLOCK;

    const float wmax = load_dim(imw_p) - 1.0f;
    const float hmax = load_dim(imh_p) - 1.0f;

    #pragma unroll
    for (int i = 0; i < 2; i++) {
        const int lr = warp * 2 + i;        // local row 0..31
        const int n  = r0 + lr;             // global row
        if (n >= N) break;

        // ---------------- softmax over 81 logits ----------------
        const float* lrow = logits + (size_t)n * 81;
        float v0 = lrow[lane];
        float v1 = lrow[lane + 32];
        float v2 = (lane < 17) ? lrow[lane + 64] : -CUDART_INF_F;

        float m = fmaxf(fmaxf(v0, v1), v2);
        #pragma unroll
        for (int o = 16; o; o >>= 1)
            m = fmaxf(m, __shfl_xor_sync(0xffffffffu, m, o));

        float e0 = __expf(v0 - m);
        float e1 = __expf(v1 - m);
        float e2 = (lane < 17) ? __expf(v2 - m) : 0.0f;

        float s = e0 + e1 + e2;
        #pragma unroll
        for (int o = 16; o; o >>= 1)
            s += __shfl_xor_sync(0xffffffffu, s, o);
        const float inv = __fdividef(1.0f, s);

        // ---------------- bbox decode (all lanes redundantly) ----------------
        const float4 b  = reinterpret_cast<const float4*>(prop)[n];
        const float4 rc = reinterpret_cast<const float4*>(regr)[n];

        const float w  = b.z - b.x + 1.0f;
        const float h  = b.w - b.y + 1.0f;
        const float cx = b.x + 0.5f * w;
        const float cy = b.y + 0.5f * h;

        const float dx = rc.x * 0.1f;
        const float dy = rc.y * 0.1f;
        const float dw = fminf(rc.z * 0.2f, BBOX_XFORM_CLIP);
        const float dh = fminf(rc.w * 0.2f, BBOX_XFORM_CLIP);

        const float pcx = dx * w + cx;
        const float pcy = dy * h + cy;
        const float pw  = __expf(dw) * w;
        const float ph  = __expf(dh) * h;

        float x1 = pcx - 0.5f * pw;
        float y1 = pcy - 0.5f * ph;
        float x2 = pcx + 0.5f * pw - 1.0f;
        float y2 = pcy + 0.5f * ph - 1.0f;

        // max(...,0) then clip(0,max) == clamp to [0,max]
        x1 = fminf(fmaxf(x1, 0.0f), wmax);
        y1 = fminf(fmaxf(y1, 0.0f), hmax);
        x2 = fminf(fmaxf(x2, 0.0f), wmax);
        y2 = fminf(fmaxf(y2, 0.0f), hmax);

        const float4 box = make_float4(x1, y1, x2, y2);

        // ---------------- stage to SMEM ----------------
        float4* sb = reinterpret_cast<float4*>(s_boxes) + lr * 81;
        sb[lane]      = box;
        sb[lane + 32] = box;
        if (lane < 17) sb[lane + 64] = box;

        float* ss = s_scores + lr * 81;
        ss[lane]      = e0 * inv;
        ss[lane + 32] = e1 * inv;
        if (lane < 17) ss[lane + 64] = e2 * inv;
    }

    __syncthreads();

    // ---------------- bulk store SMEM -> GMEM (TMA path) ----------------
    if (threadIdx.x == 0) {
        // order generic-proxy STS before async-proxy bulk read
        asm volatile("fence.proxy.async.shared::cta;" ::: "memory");

        unsigned sb_addr = (unsigned)__cvta_generic_to_shared(s_boxes);
        unsigned ss_addr = (unsigned)__cvta_generic_to_shared(s_scores);

        char* gboxes  = (char*)boxes_out  + (size_t)blockIdx.x * BOX_TILE_BYTES;
        char* gscores = (char*)scores_out + (size_t)blockIdx.x * SC_TILE_BYTES;

        asm volatile(
            "cp.async.bulk.global.shared::cta.bulk_group [%0], [%1], %2;"
            :: "l"(gboxes), "r"(sb_addr), "n"(BOX_TILE_BYTES) : "memory");
        asm volatile(
            "cp.async.bulk.global.shared::cta.bulk_group [%0], [%1], %2;"
            :: "l"(gscores), "r"(ss_addr), "n"(SC_TILE_BYTES) : "memory");
        asm volatile("cp.async.bulk.commit_group;" ::: "memory");
        // CTA must stay alive until the bulk engine has read SMEM
        asm volatile("cp.async.bulk.wait_group.read 0;" ::: "memory");
    }
}

extern "C" void kernel_launch(void* const* d_in, const int* in_sizes, int n_in,
                              void* d_out, int out_size) {
    const float* logits = (const float*)d_in[0];
    const float* regr   = (const float*)d_in[1];
    const float* prop   = (const float*)d_in[2];
    const void*  imw    = d_in[3];
    const void*  imh    = d_in[4];

    const int N = in_sizes[0] / 81;          // 262144

    float* boxes  = (float*)d_out;           // N*81*4 floats
    float* scores = boxes + (size_t)N * 81 * 4;

    const int blocks = (N + ROWS_PER_BLOCK - 1) / ROWS_PER_BLOCK;  // 8192
    postproc_kernel<<<blocks, THREADS>>>(logits, regr, prop, imw, imh,
                                         boxes, scores, N);
}

// round 6
// speedup vs baseline: 1.1795x; 1.1299x over previous
#include <cuda_runtime.h>
#include <cuda_bf16.h>
#include <math_constants.h>

// BBOX_XFORM_CLIP = log(1000/16)
#define BBOX_XFORM_CLIP 4.135166556742356f

#define HALF_ROWS 8                  // rows per half-tile (one row per warp)
#define ROWS_PER_BLOCK (2 * HALF_ROWS)
#define THREADS 256                  // 8 warps

#define BOX_HALF_BYTES (HALF_ROWS * 81 * 16)   // 10368
#define SC_HALF_BYTES  (HALF_ROWS * 81 * 4)    //  2592

// img dims may arrive as int32 or float32; disambiguate by plausibility.
__device__ __forceinline__ float load_dim(const void* p) {
    int iv = *(const int*)p;
    if (iv > 0 && iv < (1 << 20)) return (float)iv;
    return __int_as_float(iv);
}

struct RowOut {
    float4 box;
    float sc0, sc1, sc2;
};

__device__ __forceinline__ RowOut process_row(
    const float* __restrict__ logits,
    const float* __restrict__ regr,
    const float* __restrict__ prop,
    int n, int lane, float wmax, float hmax)
{
    // ---------------- softmax over 81 logits ----------------
    const float* lrow = logits + (size_t)n * 81;
    float v0 = lrow[lane];
    float v1 = lrow[lane + 32];
    float v2 = (lane < 17) ? lrow[lane + 64] : -CUDART_INF_F;

    float m = fmaxf(fmaxf(v0, v1), v2);
    #pragma unroll
    for (int o = 16; o; o >>= 1)
        m = fmaxf(m, __shfl_xor_sync(0xffffffffu, m, o));

    float e0 = __expf(v0 - m);
    float e1 = __expf(v1 - m);
    float e2 = (lane < 17) ? __expf(v2 - m) : 0.0f;

    float s = e0 + e1 + e2;
    #pragma unroll
    for (int o = 16; o; o >>= 1)
        s += __shfl_xor_sync(0xffffffffu, s, o);
    const float inv = __fdividef(1.0f, s);

    // ---------------- bbox decode (all lanes redundantly) ----------------
    const float4 b  = reinterpret_cast<const float4*>(prop)[n];
    const float4 rc = reinterpret_cast<const float4*>(regr)[n];

    const float w  = b.z - b.x + 1.0f;
    const float h  = b.w - b.y + 1.0f;
    const float cx = b.x + 0.5f * w;
    const float cy = b.y + 0.5f * h;

    const float dx = rc.x * 0.1f;
    const float dy = rc.y * 0.1f;
    const float dw = fminf(rc.z * 0.2f, BBOX_XFORM_CLIP);
    const float dh = fminf(rc.w * 0.2f, BBOX_XFORM_CLIP);

    const float pcx = dx * w + cx;
    const float pcy = dy * h + cy;
    const float pw  = __expf(dw) * w;
    const float ph  = __expf(dh) * h;

    float x1 = pcx - 0.5f * pw;
    float y1 = pcy - 0.5f * ph;
    float x2 = pcx + 0.5f * pw - 1.0f;
    float y2 = pcy + 0.5f * ph - 1.0f;

    // max(...,0) then clip(0,max) == clamp to [0,max]
    RowOut r;
    r.box = make_float4(fminf(fmaxf(x1, 0.0f), wmax),
                        fminf(fmaxf(y1, 0.0f), hmax),
                        fminf(fmaxf(x2, 0.0f), wmax),
                        fminf(fmaxf(y2, 0.0f), hmax));
    r.sc0 = e0 * inv;
    r.sc1 = e1 * inv;
    r.sc2 = e2 * inv;
    return r;
}

__device__ __forceinline__ void stage_row(float* s_box, float* s_sc,
                                          int lr, int lane, const RowOut& r)
{
    float4* sb = reinterpret_cast<float4*>(s_box) + lr * 81;
    sb[lane]      = r.box;
    sb[lane + 32] = r.box;
    if (lane < 17) sb[lane + 64] = r.box;

    float* ss = s_sc + lr * 81;
    ss[lane]      = r.sc0;
    ss[lane + 32] = r.sc1;
    if (lane < 17) ss[lane + 64] = r.sc2;
}

__device__ __forceinline__ void commit_half(const float* s_box, const float* s_sc,
                                            float* boxes_out, float* scores_out,
                                            long long half_idx)
{
    asm volatile("fence.proxy.async.shared::cta;" ::: "memory");
    unsigned sb_a = (unsigned)__cvta_generic_to_shared(s_box);
    unsigned ss_a = (unsigned)__cvta_generic_to_shared(s_sc);
    char* gb = (char*)boxes_out  + (size_t)half_idx * BOX_HALF_BYTES;
    char* gs = (char*)scores_out + (size_t)half_idx * SC_HALF_BYTES;
    asm volatile("cp.async.bulk.global.shared::cta.bulk_group [%0], [%1], %2;"
                 :: "l"(gb), "r"(sb_a), "n"(BOX_HALF_BYTES) : "memory");
    asm volatile("cp.async.bulk.global.shared::cta.bulk_group [%0], [%1], %2;"
                 :: "l"(gs), "r"(ss_a), "n"(SC_HALF_BYTES) : "memory");
    asm volatile("cp.async.bulk.commit_group;" ::: "memory");
}

__global__ void __launch_bounds__(THREADS)
postproc_kernel(const float* __restrict__ logits,       // [N,81]
                const float* __restrict__ regr,         // [N,4]
                const float* __restrict__ prop,         // [N,4]
                const void*  __restrict__ imw_p,
                const void*  __restrict__ imh_p,
                float* __restrict__ boxes_out,          // [N*81,4]
                float* __restrict__ scores_out,         // [N*81]
                int N)
{
    __shared__ alignas(16) float s_box[2][HALF_ROWS * 81 * 4];  // 2x10368 B
    __shared__ alignas(16) float s_sc [2][HALF_ROWS * 81];      // 2x 2592 B

    const int warp = threadIdx.x >> 5;
    const int lane = threadIdx.x & 31;
    const int r0   = blockIdx.x * ROWS_PER_BLOCK;

    const float wmax = load_dim(imw_p) - 1.0f;
    const float hmax = load_dim(imh_p) - 1.0f;

    if (r0 + ROWS_PER_BLOCK <= N) {
        // ---------------- half A ----------------
        {
            const int n = r0 + warp;
            RowOut r = process_row(logits, regr, prop, n, lane, wmax, hmax);
            stage_row(s_box[0], s_sc[0], warp, lane, r);
        }
        __syncthreads();
        if (threadIdx.x == 0)
            commit_half(s_box[0], s_sc[0], boxes_out, scores_out,
                        2LL * blockIdx.x);          // no wait: drains under half B

        // ---------------- half B (overlaps half A's drain) ----------------
        {
            const int n = r0 + HALF_ROWS + warp;
            RowOut r = process_row(logits, regr, prop, n, lane, wmax, hmax);
            stage_row(s_box[1], s_sc[1], warp, lane, r);
        }
        __syncthreads();
        if (threadIdx.x == 0) {
            commit_half(s_box[1], s_sc[1], boxes_out, scores_out,
                        2LL * blockIdx.x + 1);
            // CTA must stay alive until the bulk engine has read both buffers
            asm volatile("cp.async.bulk.wait_group.read 0;" ::: "memory");
        }
    } else {
        // partial tail tile (not hit when N % 16 == 0): direct stores
        #pragma unroll
        for (int i = 0; i < 2; i++) {
            const int n = r0 + i * HALF_ROWS + warp;
            if (n >= N) break;
            RowOut r = process_row(logits, regr, prop, n, lane, wmax, hmax);
            float4* bo = reinterpret_cast<float4*>(boxes_out) + (size_t)n * 81;
            bo[lane]      = r.box;
            bo[lane + 32] = r.box;
            if (lane < 17) bo[lane + 64] = r.box;
            float* so = scores_out + (size_t)n * 81;
            so[lane]      = r.sc0;
            so[lane + 32] = r.sc1;
            if (lane < 17) so[lane + 64] = r.sc2;
        }
    }
}

extern "C" void kernel_launch(void* const* d_in, const int* in_sizes, int n_in,
                              void* d_out, int out_size) {
    const float* logits = (const float*)d_in[0];
    const float* regr   = (const float*)d_in[1];
    const float* prop   = (const float*)d_in[2];
    const void*  imw    = d_in[3];
    const void*  imh    = d_in[4];

    const int N = in_sizes[0] / 81;          // 262144

    float* boxes  = (float*)d_out;           // N*81*4 floats
    float* scores = boxes + (size_t)N * 81 * 4;

    const int blocks = (N + ROWS_PER_BLOCK - 1) / ROWS_PER_BLOCK;  // 16384
    postproc_kernel<<<blocks, THREADS>>>(logits, regr, prop, imw, imh,
                                         boxes, scores, N);
}